// round 4
// baseline (speedup 1.0000x reference)
#include <cuda_runtime.h>
#include <cuda_bf16.h>

// PointMatcher: pred (N=1024,20,2) vs gt (M=2048,20,2)
// dist(i,j) = mean_p ||pred[i,p]-gt[j,p]|| ; argmin over j per i.
// Outputs concatenated in d_out (float32):
//   [0..N*40) matched gt rows | [N*40..N*41) confidence | [N*41..N*42) indices

#define BI      4       // pred rows per block
#define TJ      256     // gt rows per tile
#define P       20
#define ROWF    40      // floats per row
#define ROWP    44      // padded shared stride (16B-aligned rows)
#define THREADS 512
#define TILEF   (TJ * ROWP)          // floats per buffer (11264)
#define SMEM_BYTES (2*TILEF*4 + BI*P*8 + BI*8)

typedef unsigned long long ull;

__device__ __forceinline__ float fsqrt_approx(float x) {
    float r;
    asm("sqrt.approx.f32 %0, %1;" : "=f"(r) : "f"(x));
    return r;
}
__device__ __forceinline__ void cp_async16(float* dst, const float* src) {
    unsigned sa = (unsigned)__cvta_generic_to_shared(dst);
    asm volatile("cp.async.cg.shared.global [%0], [%1], 16;" :: "r"(sa), "l"(src));
}

__global__ __launch_bounds__(THREADS, 2)
void pointmatcher_kernel(const float* __restrict__ pred,
                         const float* __restrict__ gt,
                         float* __restrict__ out_mp,
                         float* __restrict__ out_conf,
                         float* __restrict__ out_idx,
                         int N, int M)
{
    extern __shared__ float smem[];
    float* buf[2] = { smem, smem + TILEF };
    ull*   spred  = (ull*)(smem + 2 * TILEF);          // [BI][P] packed {-x,-y}
    ull*   best   = (ull*)(spred + BI * P);

    const int tid = threadIdx.x;
    const int il  = tid & (BI - 1);
    const int jl  = tid >> 2;                          // 0..127, rows 2jl, 2jl+1

    if (tid < BI) best[tid] = ~0ull;
    if (tid < BI * P) {                                // pre-negated packed pred
        int pi = tid / P, pp = tid - pi * P;
        float2 v = ((const float2*)(pred + (size_t)(blockIdx.x * BI + pi) * ROWF))[pp];
        float nx = -v.x, ny = -v.y;
        ull pk;
        asm("mov.b64 %0, {%1,%2};" : "=l"(pk) : "f"(nx), "f"(ny));
        spred[tid] = pk;
    }

    // prefetch tile 0
    {
        const float* src = gt;
        #pragma unroll
        for (int it = 0; it < 5; it++) {
            int f = tid + it * THREADS;                // float4 index 0..2559
            int row = f / 10, k4 = f - row * 10;
            cp_async16(buf[0] + row * ROWP + k4 * 4, src + f * 4);
        }
        asm volatile("cp.async.commit_group;");
    }

    float minv = 3.402823466e+38f;                     // min of SUM (mean deferred)
    int   minj = 0;
    const int ntiles = M / TJ;                         // 8

    for (int t = 0; t < ntiles; t++) {
        asm volatile("cp.async.wait_group 0;");
        __syncthreads();   // tile t ready everywhere; compute t-1 done on other buf

        if (t + 1 < ntiles) {                          // prefetch next tile
            const float* src = gt + (size_t)(t + 1) * TJ * ROWF;
            float* dst = buf[(t + 1) & 1];
            #pragma unroll
            for (int it = 0; it < 5; it++) {
                int f = tid + it * THREADS;
                int row = f / 10, k4 = f - row * 10;
                cp_async16(dst + row * ROWP + k4 * 4, src + f * 4);
            }
        }
        asm volatile("cp.async.commit_group;");        // (empty group ok on last tile)

        const ull* r0 = (const ull*)(buf[t & 1] + (2 * jl) * ROWP);
        const ull* r1 = (const ull*)(buf[t & 1] + (2 * jl + 1) * ROWP);
        const ull* pn = spred + il * P;

        ull acc = 0;                                   // packed {sum0, sum1}
        #pragma unroll
        for (int p = 0; p < P; p++) {
            ull g0 = r0[p];                            // {x,y} row 2jl
            ull g1 = r1[p];                            // {x,y} row 2jl+1
            ull pk = pn[p];                            // {-x,-y}
            ull d0, d1, q0, q1;
            asm("add.rn.f32x2 %0, %1, %2;" : "=l"(d0) : "l"(g0), "l"(pk));
            asm("add.rn.f32x2 %0, %1, %2;" : "=l"(d1) : "l"(g1), "l"(pk));
            asm("mul.rn.f32x2 %0, %1, %2;" : "=l"(q0) : "l"(d0), "l"(d0));
            asm("mul.rn.f32x2 %0, %1, %2;" : "=l"(q1) : "l"(d1), "l"(d1));
            float a0, b0, a1, b1;
            asm("mov.b64 {%0,%1}, %2;" : "=f"(a0), "=f"(b0) : "l"(q0));
            asm("mov.b64 {%0,%1}, %2;" : "=f"(a1), "=f"(b1) : "l"(q1));
            float s0 = a0 + b0;
            float s1 = a1 + b1;
            float w0 = fsqrt_approx(s0);
            float w1 = fsqrt_approx(s1);
            ull rpk;
            asm("mov.b64 %0, {%1,%2};" : "=l"(rpk) : "f"(w0), "f"(w1));
            asm("add.rn.f32x2 %0, %1, %2;" : "=l"(acc) : "l"(acc), "l"(rpk));
        }
        float s0, s1;
        asm("mov.b64 {%0,%1}, %2;" : "=f"(s0), "=f"(s1) : "l"(acc));
        int j0 = t * TJ + 2 * jl;
        if (s0 < minv) { minv = s0; minj = j0; }       // ascending j, '<' keeps
        if (s1 < minv) { minv = s1; minj = j0 + 1; }   // first tie = argmin
    }

    // Block argmin: packed (dist_bits, j); min == (min dist, then min j).
    ull key = ((ull)__float_as_uint(minv) << 32) | (unsigned)minj;
    atomicMin(&best[il], key);
    __syncthreads();

    if (tid < BI) {
        ull b = best[tid];
        int j = (int)(unsigned)b;
        float md = __uint_as_float((unsigned)(b >> 32)) * (1.0f / (float)P);
        int row = blockIdx.x * BI + tid;
        out_conf[row] = (md > 2.0f) ? 0.0f : expf(-md);
        out_idx[row]  = (float)j;
    }
    if (tid < BI * ROWF) {
        int ilg = tid / ROWF;
        int k   = tid - ilg * ROWF;
        int j   = (int)(unsigned)best[ilg];
        out_mp[(blockIdx.x * BI + ilg) * ROWF + k] = gt[(size_t)j * ROWF + k];
    }
}

extern "C" void kernel_launch(void* const* d_in, const int* in_sizes, int n_in,
                              void* d_out, int out_size)
{
    const float* pred = (const float*)d_in[0];
    const float* gt   = (const float*)d_in[1];
    float* out        = (float*)d_out;

    int N = in_sizes[0] / ROWF;   // 1024
    int M = in_sizes[1] / ROWF;   // 2048

    float* out_mp   = out;
    float* out_conf = out + (size_t)N * ROWF;
    float* out_idx  = out + (size_t)N * ROWF + N;

    static bool attr_set = false;  // host-side only; not part of captured graph
    if (!attr_set) {
        cudaFuncSetAttribute(pointmatcher_kernel,
                             cudaFuncAttributeMaxDynamicSharedMemorySize,
                             SMEM_BYTES);
        attr_set = true;
    }

    pointmatcher_kernel<<<N / BI, THREADS, SMEM_BYTES>>>(
        pred, gt, out_mp, out_conf, out_idx, N, M);
}

// round 5
// speedup vs baseline: 1.5941x; 1.5941x over previous
#include <cuda_runtime.h>
#include <cuda_bf16.h>

// PointMatcher: pred (N=1024,20,2) vs gt (M=2048,20,2)
// dist(i,j) = mean_p ||pred[i,p]-gt[j,p]|| ; argmin over j per i.
// Outputs concatenated in d_out (float32):
//   [0..N*40) matched gt rows | [N*40..N*41) confidence | [N*41..N*42) indices

#define BI      4       // pred rows per block
#define TJ      256     // gt rows per tile
#define P       20
#define ROWF    40      // floats per row
#define ROWP    44      // padded shared stride (16B-aligned rows)
#define THREADS 512
#define TILEF   (TJ * ROWP)          // floats per buffer (11264)
#define SMEM_BYTES (2*TILEF*4 + BI*P*8 + BI*8)

typedef unsigned long long ull;

__device__ __forceinline__ float fsqrt_approx(float x) {
    float r;
    asm("sqrt.approx.f32 %0, %1;" : "=f"(r) : "f"(x));
    return r;
}
__device__ __forceinline__ void cp_async16(float* dst, const float* src) {
    unsigned sa = (unsigned)__cvta_generic_to_shared(dst);
    asm volatile("cp.async.cg.shared.global [%0], [%1], 16;" :: "r"(sa), "l"(src));
}

__global__ __launch_bounds__(THREADS, 2)
void pointmatcher_kernel(const float* __restrict__ pred,
                         const float* __restrict__ gt,
                         float* __restrict__ out_mp,
                         float* __restrict__ out_conf,
                         float* __restrict__ out_idx,
                         int N, int M)
{
    extern __shared__ float smem[];
    float* buf[2] = { smem, smem + TILEF };
    ull*   spred  = (ull*)(smem + 2 * TILEF);          // [BI][P] packed {-x,-y}
    ull*   best   = (ull*)(spred + BI * P);

    const int tid = threadIdx.x;
    const int il  = tid & (BI - 1);
    const int jl  = tid >> 2;                          // 0..127, rows 2jl, 2jl+1

    if (tid < BI) best[tid] = ~0ull;
    if (tid < BI * P) {                                // pre-negated packed pred
        int pi = tid / P, pp = tid - pi * P;
        float2 v = ((const float2*)(pred + (size_t)(blockIdx.x * BI + pi) * ROWF))[pp];
        float nx = -v.x, ny = -v.y;
        ull pk;
        asm("mov.b64 %0, {%1,%2};" : "=l"(pk) : "f"(nx), "f"(ny));
        spred[tid] = pk;
    }

    // prefetch tile 0
    {
        const float* src = gt;
        #pragma unroll
        for (int it = 0; it < 5; it++) {
            int f = tid + it * THREADS;                // float4 index 0..2559
            int row = f / 10, k4 = f - row * 10;
            cp_async16(buf[0] + row * ROWP + k4 * 4, src + f * 4);
        }
        asm volatile("cp.async.commit_group;");
    }

    float minv = 3.402823466e+38f;                     // min of SUM (mean deferred)
    int   minj = 0;
    const int ntiles = M / TJ;                         // 8

    for (int t = 0; t < ntiles; t++) {
        asm volatile("cp.async.wait_group 0;");
        __syncthreads();   // tile t ready everywhere; compute t-1 done on other buf

        if (t + 1 < ntiles) {                          // prefetch next tile
            const float* src = gt + (size_t)(t + 1) * TJ * ROWF;
            float* dst = buf[(t + 1) & 1];
            #pragma unroll
            for (int it = 0; it < 5; it++) {
                int f = tid + it * THREADS;
                int row = f / 10, k4 = f - row * 10;
                cp_async16(dst + row * ROWP + k4 * 4, src + f * 4);
            }
        }
        asm volatile("cp.async.commit_group;");        // (empty group ok on last tile)

        const ull* r0 = (const ull*)(buf[t & 1] + (2 * jl) * ROWP);
        const ull* r1 = (const ull*)(buf[t & 1] + (2 * jl + 1) * ROWP);
        const ull* pn = spred + il * P;

        ull acc = 0;                                   // packed {sum0, sum1}
        #pragma unroll
        for (int p = 0; p < P; p++) {
            ull g0 = r0[p];                            // {x,y} row 2jl
            ull g1 = r1[p];                            // {x,y} row 2jl+1
            ull pk = pn[p];                            // {-x,-y}
            ull d0, d1, q0, q1;
            asm("add.rn.f32x2 %0, %1, %2;" : "=l"(d0) : "l"(g0), "l"(pk));
            asm("add.rn.f32x2 %0, %1, %2;" : "=l"(d1) : "l"(g1), "l"(pk));
            asm("mul.rn.f32x2 %0, %1, %2;" : "=l"(q0) : "l"(d0), "l"(d0));
            asm("mul.rn.f32x2 %0, %1, %2;" : "=l"(q1) : "l"(d1), "l"(d1));
            float a0, b0, a1, b1;
            asm("mov.b64 {%0,%1}, %2;" : "=f"(a0), "=f"(b0) : "l"(q0));
            asm("mov.b64 {%0,%1}, %2;" : "=f"(a1), "=f"(b1) : "l"(q1));
            float s0 = a0 + b0;
            float s1 = a1 + b1;
            float w0 = fsqrt_approx(s0);
            float w1 = fsqrt_approx(s1);
            ull rpk;
            asm("mov.b64 %0, {%1,%2};" : "=l"(rpk) : "f"(w0), "f"(w1));
            asm("add.rn.f32x2 %0, %1, %2;" : "=l"(acc) : "l"(acc), "l"(rpk));
        }
        float s0, s1;
        asm("mov.b64 {%0,%1}, %2;" : "=f"(s0), "=f"(s1) : "l"(acc));
        int j0 = t * TJ + 2 * jl;
        if (s0 < minv) { minv = s0; minj = j0; }       // ascending j, '<' keeps
        if (s1 < minv) { minv = s1; minj = j0 + 1; }   // first tie = argmin
    }

    // Block argmin: packed (dist_bits, j); min == (min dist, then min j).
    ull key = ((ull)__float_as_uint(minv) << 32) | (unsigned)minj;
    atomicMin(&best[il], key);
    __syncthreads();

    if (tid < BI) {
        ull b = best[tid];
        int j = (int)(unsigned)b;
        float md = __uint_as_float((unsigned)(b >> 32)) * (1.0f / (float)P);
        int row = blockIdx.x * BI + tid;
        out_conf[row] = (md > 2.0f) ? 0.0f : expf(-md);
        out_idx[row]  = (float)j;
    }
    if (tid < BI * ROWF) {
        int ilg = tid / ROWF;
        int k   = tid - ilg * ROWF;
        int j   = (int)(unsigned)best[ilg];
        out_mp[(blockIdx.x * BI + ilg) * ROWF + k] = gt[(size_t)j * ROWF + k];
    }
}

extern "C" void kernel_launch(void* const* d_in, const int* in_sizes, int n_in,
                              void* d_out, int out_size)
{
    const float* pred = (const float*)d_in[0];
    const float* gt   = (const float*)d_in[1];
    float* out        = (float*)d_out;

    int N = in_sizes[0] / ROWF;   // 1024
    int M = in_sizes[1] / ROWF;   // 2048

    float* out_mp   = out;
    float* out_conf = out + (size_t)N * ROWF;
    float* out_idx  = out + (size_t)N * ROWF + N;

    static bool attr_set = false;  // host-side only; not part of captured graph
    if (!attr_set) {
        cudaFuncSetAttribute(pointmatcher_kernel,
                             cudaFuncAttributeMaxDynamicSharedMemorySize,
                             SMEM_BYTES);
        attr_set = true;
    }

    pointmatcher_kernel<<<N / BI, THREADS, SMEM_BYTES>>>(
        pred, gt, out_mp, out_conf, out_idx, N, M);
}